// round 14
// baseline (speedup 1.0000x reference)
#include <cuda_runtime.h>
#include <cuda_bf16.h>
#include <float.h>

#define THREADS 384
// ---- smem byte offsets ----
#define AHI_OFF 0          // x / attn-out hi [64][200] bf16
#define ALO_OFF 25600
#define WST_OFF 51200      // W stage [2buf][2hl][192][48B] = 36864 ; mask aliases here
#define KHI_OFF 88064      // K [56][200] bf16
#define KLO_OFF 110464
#define VTH_OFF 132864     // V^T [192][72] bf16 (dim-major, token minor)
#define VTL_OFF 160512
#define SMEM_BYTES 188160
#define KSTR 200
#define VSTR 72

__device__ __nv_bfloat16 g_Whi[110592];
__device__ __nv_bfloat16 g_Wlo[110592];
__device__ __nv_bfloat16 g_Phi[36864];
__device__ __nv_bfloat16 g_Plo[36864];

__global__ void prep_weights(const float* __restrict__ qkv_w,
                             const float* __restrict__ proj_w) {
    int i = blockIdx.x * 256 + threadIdx.x;
    if (i < 110592) {
        float v = qkv_w[i];
        __nv_bfloat16 h = __float2bfloat16(v);
        g_Whi[i] = h;
        g_Wlo[i] = __float2bfloat16(v - __bfloat162float(h));
    }
    if (i < 36864) {
        float v = proj_w[i];
        __nv_bfloat16 h = __float2bfloat16(v);
        g_Phi[i] = h;
        g_Plo[i] = __float2bfloat16(v - __bfloat162float(h));
    }
}

__device__ __forceinline__ unsigned pkbf(__nv_bfloat16 a, __nv_bfloat16 b) {
    return (unsigned)__bfloat16_as_ushort(a) | ((unsigned)__bfloat16_as_ushort(b) << 16);
}
__device__ __forceinline__ void split2(float x, float y, unsigned& hi, unsigned& lo) {
    __nv_bfloat16 h0 = __float2bfloat16(x), h1 = __float2bfloat16(y);
    __nv_bfloat16 l0 = __float2bfloat16(x - __bfloat162float(h0));
    __nv_bfloat16 l1 = __float2bfloat16(y - __bfloat162float(h1));
    hi = pkbf(h0, h1);
    lo = pkbf(l0, l1);
}
__device__ __forceinline__ void mma_bf16(float* c, const unsigned* a, const unsigned* b) {
    asm volatile(
        "mma.sync.aligned.m16n8k16.row.col.f32.bf16.bf16.f32 "
        "{%0,%1,%2,%3}, {%4,%5,%6,%7}, {%8,%9}, {%0,%1,%2,%3};\n"
        : "+f"(c[0]), "+f"(c[1]), "+f"(c[2]), "+f"(c[3])
        : "r"(a[0]), "r"(a[1]), "r"(a[2]), "r"(a[3]), "r"(b[0]), "r"(b[1]));
}
__device__ __forceinline__ void ldsm4(unsigned* r, unsigned addr) {
    asm volatile("ldmatrix.sync.aligned.m8n8.x4.shared.b16 {%0,%1,%2,%3}, [%4];\n"
                 : "=r"(r[0]), "=r"(r[1]), "=r"(r[2]), "=r"(r[3]) : "r"(addr));
}
__device__ __forceinline__ void ldsm2(unsigned* r, unsigned addr) {
    asm volatile("ldmatrix.sync.aligned.m8n8.x2.shared.b16 {%0,%1}, [%2];\n"
                 : "=r"(r[0]), "=r"(r[1]) : "r"(addr));
}

// ---- generic GEMM: C[49][192] = A(hi+lo)[64][192] @ W^T + bias, scaled ----
// MODE 0: fp32 -> outp (stride 192).  MODE 1: RoPE -> bf16 hi/lo (stride KSTR).
// MODE 2: transposed -> V^T [192][VSTR] bf16 hi/lo.
template <int MODE>
__device__ __noinline__ void gemm_mma(const __nv_bfloat16* __restrict__ Whi,
                                      const __nv_bfloat16* __restrict__ Wlo,
                                      const float* __restrict__ bias, float scale,
                                      float* __restrict__ outp,
                                      __nv_bfloat16* __restrict__ ohi,
                                      __nv_bfloat16* __restrict__ olo,
                                      const float* __restrict__ rope) {
    extern __shared__ char smem[];
    char* wst = smem + WST_OFF;
    const unsigned smem_u32 = (unsigned)__cvta_generic_to_shared(smem);
    const unsigned wst_u32 = smem_u32 + WST_OFF;

    const int tid = threadIdx.x;
    const int wid = tid >> 5, lane = tid & 31;
    const int g = lane >> 2, tig = lane & 3;
    const int mt = wid & 3;          // 16-row tile
    const int nq = wid >> 2;         // 64-col third
    const int grp = lane >> 3;
    const unsigned lm_off = (unsigned)(((grp >> 1) * 8 + (lane & 7)) * 48 + (grp & 1) * 16);

    // A ldmatrix per-lane address (x4: m0 rows r0 k0 | m1 rows r0+8 k0 | m2 r0 k8 | m3 r0+8 k8)
    const int a_row = mt * 16 + ((grp & 1) << 3) + (lane & 7);
    const int a_col = (grp >> 1) << 3;
    const unsigned a_h = smem_u32 + AHI_OFF + (unsigned)((a_row * 200 + a_col) * 2);
    const unsigned a_l = smem_u32 + ALO_OFF + (unsigned)((a_row * 200 + a_col) * 2);

    const int n0 = tid % 192, hf0 = (tid / 192) & 1;
    const int i1 = tid + 384;
    const int n1 = i1 % 192, hf1 = (i1 / 192) & 1;

    float acc[8][4];
    #pragma unroll
    for (int t = 0; t < 8; t++) { acc[t][0]=acc[t][1]=acc[t][2]=acc[t][3]=0.f; }

    {   // stage k-panel 0
        float4 v = *reinterpret_cast<const float4*>(Whi + n0 * 192 + hf0 * 8);
        *reinterpret_cast<float4*>(wst + n0 * 48 + hf0 * 16) = v;
        float4 w = *reinterpret_cast<const float4*>(Wlo + n1 * 192 + hf1 * 8);
        *reinterpret_cast<float4*>(wst + 9216 + n1 * 48 + hf1 * 16) = w;
    }
    __syncthreads();

    for (int k = 0; k < 12; k++) {
        const int buf = k & 1;
        float4 pf0, pf1;
        if (k < 11) {
            pf0 = *reinterpret_cast<const float4*>(Whi + n0 * 192 + (k + 1) * 16 + hf0 * 8);
            pf1 = *reinterpret_cast<const float4*>(Wlo + n1 * 192 + (k + 1) * 16 + hf1 * 8);
        }
        unsigned ahi[4], alo[4];
        ldsm4(ahi, a_h + (unsigned)(k * 32));
        ldsm4(alo, a_l + (unsigned)(k * 32));
        const unsigned base_h = wst_u32 + (unsigned)(buf * 18432) + lm_off;
        #pragma unroll
        for (int p = 0; p < 4; p++) {
            unsigned bh[4], bl[4];
            unsigned ad = base_h + (unsigned)((nq * 64 + 16 * p) * 48);
            ldsm4(bh, ad);
            ldsm4(bl, ad + 9216);
            mma_bf16(acc[2 * p], ahi, bh);
            mma_bf16(acc[2 * p], ahi, bl);
            mma_bf16(acc[2 * p], alo, bh);
            mma_bf16(acc[2 * p + 1], ahi, bh + 2);
            mma_bf16(acc[2 * p + 1], ahi, bl + 2);
            mma_bf16(acc[2 * p + 1], alo, bh + 2);
        }
        if (k < 11) {
            *reinterpret_cast<float4*>(wst + (buf ^ 1) * 18432 + n0 * 48 + hf0 * 16) = pf0;
            *reinterpret_cast<float4*>(wst + (buf ^ 1) * 18432 + 9216 + n1 * 48 + hf1 * 16) = pf1;
            __syncthreads();
        }
    }

    const int r0 = mt * 16 + g;
    #pragma unroll
    for (int t = 0; t < 8; t++) {
        const int col = nq * 64 + t * 8 + 2 * tig;
        float2 bb = *reinterpret_cast<const float2*>(&bias[col]);
        float fx = 0.f, fy = 0.f;
        if (MODE == 1) {
            int hh = col >> 5, d = (col & 31) >> 1;
            fx = rope[hh * 16 + d];
            fy = rope[96 + hh * 16 + d];
        }
        #pragma unroll
        for (int half = 0; half < 2; half++) {
            const int r = r0 + half * 8;
            if (r < 49) {
                float vx = (acc[t][half * 2 + 0] + bb.x) * scale;
                float vy = (acc[t][half * 2 + 1] + bb.y) * scale;
                if (MODE == 0) {
                    *reinterpret_cast<float2*>(&outp[r * 192 + col]) = make_float2(vx, vy);
                } else if (MODE == 1) {
                    float ang = (float)(r % 7) * fx + (float)(r / 7) * fy;
                    float sv, cv;
                    sincosf(ang, &sv, &cv);
                    float re = vx * cv - vy * sv;
                    float im = vx * sv + vy * cv;
                    unsigned hi, lo;
                    split2(re, im, hi, lo);
                    *(unsigned*)&ohi[r * KSTR + col] = hi;
                    *(unsigned*)&olo[r * KSTR + col] = lo;
                } else {
                    __nv_bfloat16 h0 = __float2bfloat16(vx);
                    __nv_bfloat16 l0 = __float2bfloat16(vx - __bfloat162float(h0));
                    __nv_bfloat16 h1 = __float2bfloat16(vy);
                    __nv_bfloat16 l1 = __float2bfloat16(vy - __bfloat162float(h1));
                    ohi[col * VSTR + r] = h0;
                    olo[col * VSTR + r] = l0;
                    ohi[(col + 1) * VSTR + r] = h1;
                    olo[(col + 1) * VSTR + r] = l1;
                }
            }
        }
    }
}

__global__ void __launch_bounds__(THREADS, 1)
swin_fused_kernel(const float* __restrict__ x,
                  const float* __restrict__ mask,
                  const float* __restrict__ qkv_b,
                  const float* __restrict__ proj_b,
                  const float* __restrict__ rope,
                  float* __restrict__ out)
{
    extern __shared__ char smem[];
    __nv_bfloat16* Ah   = (__nv_bfloat16*)(smem + AHI_OFF);
    __nv_bfloat16* Al   = (__nv_bfloat16*)(smem + ALO_OFF);
    __nv_bfloat16* Khi  = (__nv_bfloat16*)(smem + KHI_OFF);
    __nv_bfloat16* Klo  = (__nv_bfloat16*)(smem + KLO_OFF);
    float* MSK = (float*)(smem + WST_OFF);
    const unsigned smem_u32 = (unsigned)__cvta_generic_to_shared(smem);
    const int tid = threadIdx.x;
    const int b = blockIdx.x;
    const int lane = tid & 31, wid = tid >> 5;
    const int g = lane >> 2, tig = lane & 3;
    const int grp = lane >> 3;
    const int mt = wid & 3, hh0 = wid >> 2;

    // ---- prologue: x -> A hi/lo, pads, zero V^T ----
    for (int i = tid; i < 4704; i += THREADS) {
        int n = i / 96, c = i % 96;
        float2 v = *reinterpret_cast<const float2*>(&x[(size_t)b * 9408 + n * 192 + 2 * c]);
        unsigned hi, lo;
        split2(v.x, v.y, hi, lo);
        *(unsigned*)&Ah[n * 200 + 2 * c] = hi;
        *(unsigned*)&Al[n * 200 + 2 * c] = lo;
    }
    for (int i = tid; i < 15 * 96; i += THREADS) {     // A pad rows 49..63
        int r = 49 + i / 96, c = i % 96;
        *(unsigned*)&Ah[r * 200 + 2 * c] = 0u;
        *(unsigned*)&Al[r * 200 + 2 * c] = 0u;
    }
    for (int i = tid; i < 7 * 96; i += THREADS) {      // K pad rows 49..55
        int r = 49 + i / 96, c = i % 96;
        *(unsigned*)&Khi[r * KSTR + 2 * c] = 0u;
        *(unsigned*)&Klo[r * KSTR + 2 * c] = 0u;
    }
    {   // zero V^T hi+lo: 2 * 27648 B
        float4* vz = reinterpret_cast<float4*>(smem + VTH_OFF);
        for (int i = tid; i < 3456; i += THREADS) vz[i] = make_float4(0.f, 0.f, 0.f, 0.f);
    }
    // (gemm's first internal __syncthreads orders the fills)

    // ---- Q GEMM, slot-tiled: each warp owns slots (hh0,mt) and (hh0+3,mt) ----
    // Q fragments stay in registers (qh/ql), already RoPE'd and split.
    unsigned qh[2][2][4], ql[2][2][4];
    {
        char* wst = smem + WST_OFF;
        const unsigned wst_u32 = smem_u32 + WST_OFF;
        const unsigned lm_off = (unsigned)(((grp >> 1) * 8 + (lane & 7)) * 48 + (grp & 1) * 16);
        const int a_row = mt * 16 + ((grp & 1) << 3) + (lane & 7);
        const int a_col = (grp >> 1) << 3;
        const unsigned a_h = smem_u32 + AHI_OFF + (unsigned)((a_row * 200 + a_col) * 2);
        const unsigned a_l = smem_u32 + ALO_OFF + (unsigned)((a_row * 200 + a_col) * 2);
        const int n0 = tid % 192, hf0 = (tid / 192) & 1;
        const int i1 = tid + 384;
        const int n1 = i1 % 192, hf1 = (i1 / 192) & 1;

        float acc[2][4][4];
        #pragma unroll
        for (int s = 0; s < 2; s++)
            #pragma unroll
            for (int t = 0; t < 4; t++) { acc[s][t][0]=acc[s][t][1]=acc[s][t][2]=acc[s][t][3]=0.f; }

        {   // stage k-panel 0
            float4 v = *reinterpret_cast<const float4*>(g_Whi + n0 * 192 + hf0 * 8);
            *reinterpret_cast<float4*>(wst + n0 * 48 + hf0 * 16) = v;
            float4 w = *reinterpret_cast<const float4*>(g_Wlo + n1 * 192 + hf1 * 8);
            *reinterpret_cast<float4*>(wst + 9216 + n1 * 48 + hf1 * 16) = w;
        }
        __syncthreads();
        for (int k = 0; k < 12; k++) {
            const int buf = k & 1;
            float4 pf0, pf1;
            if (k < 11) {
                pf0 = *reinterpret_cast<const float4*>(g_Whi + n0 * 192 + (k + 1) * 16 + hf0 * 8);
                pf1 = *reinterpret_cast<const float4*>(g_Wlo + n1 * 192 + (k + 1) * 16 + hf1 * 8);
            }
            unsigned ahi[4], alo[4];
            ldsm4(ahi, a_h + (unsigned)(k * 32));
            ldsm4(alo, a_l + (unsigned)(k * 32));
            const unsigned base_h = wst_u32 + (unsigned)(buf * 18432) + lm_off;
            #pragma unroll
            for (int s = 0; s < 2; s++) {
                const int hh = hh0 + 3 * s;
                #pragma unroll
                for (int p = 0; p < 2; p++) {
                    unsigned bh[4], bl[4];
                    unsigned ad = base_h + (unsigned)((hh * 32 + 16 * p) * 48);
                    ldsm4(bh, ad);
                    ldsm4(bl, ad + 9216);
                    mma_bf16(acc[s][2 * p], ahi, bh);
                    mma_bf16(acc[s][2 * p], ahi, bl);
                    mma_bf16(acc[s][2 * p], alo, bh);
                    mma_bf16(acc[s][2 * p + 1], ahi, bh + 2);
                    mma_bf16(acc[s][2 * p + 1], ahi, bl + 2);
                    mma_bf16(acc[s][2 * p + 1], alo, bh + 2);
                }
            }
            if (k < 11) {
                *reinterpret_cast<float4*>(wst + (buf ^ 1) * 18432 + n0 * 48 + hf0 * 16) = pf0;
                *reinterpret_cast<float4*>(wst + (buf ^ 1) * 18432 + 9216 + n1 * 48 + hf1 * 16) = pf1;
                __syncthreads();
            }
        }
        // epilogue: bias + scale + RoPE, split to Q fragments in registers
        const int r0q = mt * 16 + g;
        #pragma unroll
        for (int s = 0; s < 2; s++) {
            const int hh = hh0 + 3 * s;
            #pragma unroll
            for (int t = 0; t < 4; t++) {
                const int col = hh * 32 + t * 8 + 2 * tig;
                float2 bb = *reinterpret_cast<const float2*>(&qkv_b[col]);
                const int d = 4 * t + tig;
                float fx = rope[hh * 16 + d];
                float fy = rope[96 + hh * 16 + d];
                #pragma unroll
                for (int half = 0; half < 2; half++) {
                    const int r = r0q + half * 8;
                    float vx = (acc[s][t][half * 2 + 0] + bb.x) * 0.17677669529663687f;
                    float vy = (acc[s][t][half * 2 + 1] + bb.y) * 0.17677669529663687f;
                    float ang = (float)(r % 7) * fx + (float)(r / 7) * fy;
                    float sv, cv;
                    sincosf(ang, &sv, &cv);
                    float re = vx * cv - vy * sv;
                    float im = vx * sv + vy * cv;
                    split2(re, im, qh[s][t >> 1][(t & 1) * 2 + half],
                           ql[s][t >> 1][(t & 1) * 2 + half]);
                }
            }
        }
    }
    __syncthreads();   // Q gemm's WST reads done before K gemm restages

    gemm_mma<1>(g_Whi + 36864, g_Wlo + 36864, qkv_b + 192, 1.0f,
                nullptr, Khi, Klo, rope);
    __syncthreads();
    gemm_mma<2>(g_Whi + 73728, g_Wlo + 73728, qkv_b + 384, 1.0f, nullptr,
                (__nv_bfloat16*)(smem + VTH_OFF), (__nv_bfloat16*)(smem + VTL_OFF), nullptr);
    __syncthreads();   // V^T + K written; WST free

    {   // stage shift mask
        const float* mrow = mask + (size_t)(b & 63) * 2401;
        for (int i = tid; i < 2401; i += THREADS) MSK[i] = mrow[i];
    }
    __syncthreads();

    // ---- barrier-free attention ----
    const int krc = ((grp >> 1) << 3) + (lane & 7);     // row-in-pair-block
    const int kcol8 = (grp & 1) << 3;
    const unsigned khi_u32 = smem_u32 + KHI_OFF;
    const unsigned klo_u32 = smem_u32 + KLO_OFF;
    const unsigned vth_u32 = smem_u32 + VTH_OFF;
    const unsigned vtl_u32 = smem_u32 + VTL_OFF;
    const int r0 = mt * 16 + g;
    const int r1 = r0 + 8;

    #pragma unroll 1
    for (int si = 0; si < 2; si++) {
        const int hh = hh0 + 3 * si;
        float c[8][4];
        #pragma unroll
        for (int t = 0; t < 7; t++) { c[t][0]=c[t][1]=c[t][2]=c[t][3]=0.f; }
        c[7][0] = c[7][1] = c[7][2] = c[7][3] = -FLT_MAX;

        // logits: Q (registers) @ K^T (ldmatrix)
        #pragma unroll
        for (int kc = 0; kc < 2; kc++) {
            const int kb0 = hh * 32 + kc * 16;
            #pragma unroll
            for (int tp = 0; tp < 3; tp++) {
                unsigned kh4[4], kl4[4];
                unsigned ad = (unsigned)(((16 * tp + krc) * KSTR + kb0 + kcol8) * 2);
                ldsm4(kh4, khi_u32 + ad);
                ldsm4(kl4, klo_u32 + ad);
                mma_bf16(c[2 * tp], qh[si][kc], kh4);
                mma_bf16(c[2 * tp], qh[si][kc], kl4);
                mma_bf16(c[2 * tp], ql[si][kc], kh4);
                mma_bf16(c[2 * tp + 1], qh[si][kc], kh4 + 2);
                mma_bf16(c[2 * tp + 1], qh[si][kc], kl4 + 2);
                mma_bf16(c[2 * tp + 1], ql[si][kc], kh4 + 2);
            }
            {   // tile 6 (rows 48..55) via x2
                unsigned kh2[2], kl2[2];
                unsigned ad = (unsigned)(((48 + (lane & 7)) * KSTR + kb0 + ((grp & 1) << 3)) * 2);
                ldsm2(kh2, khi_u32 + ad);
                ldsm2(kl2, klo_u32 + ad);
                mma_bf16(c[6], qh[si][kc], kh2);
                mma_bf16(c[6], qh[si][kc], kl2);
                mma_bf16(c[6], ql[si][kc], kh2);
            }
        }
        // mask + column bounds
        #pragma unroll
        for (int t = 0; t < 7; t++) {
            const int col = t * 8 + 2 * tig;
            if (col < 49) {
                if (r0 < 49) c[t][0] += MSK[r0 * 49 + col];
                if (r1 < 49) c[t][2] += MSK[r1 * 49 + col];
            } else { c[t][0] = -FLT_MAX; c[t][2] = -FLT_MAX; }
            if (col + 1 < 49) {
                if (r0 < 49) c[t][1] += MSK[r0 * 49 + col + 1];
                if (r1 < 49) c[t][3] += MSK[r1 * 49 + col + 1];
            } else { c[t][1] = -FLT_MAX; c[t][3] = -FLT_MAX; }
        }
        // softmax (row lives in a quad: 2 shuffles)
        {
            float mx0 = -FLT_MAX, mx1 = -FLT_MAX;
            #pragma unroll
            for (int t = 0; t < 8; t++) {
                mx0 = fmaxf(mx0, fmaxf(c[t][0], c[t][1]));
                mx1 = fmaxf(mx1, fmaxf(c[t][2], c[t][3]));
            }
            #pragma unroll
            for (int o = 1; o <= 2; o <<= 1) {
                mx0 = fmaxf(mx0, __shfl_xor_sync(~0u, mx0, o));
                mx1 = fmaxf(mx1, __shfl_xor_sync(~0u, mx1, o));
            }
            float s0 = 0.f, s1 = 0.f;
            #pragma unroll
            for (int t = 0; t < 8; t++) {
                c[t][0] = __expf(c[t][0] - mx0); s0 += c[t][0];
                c[t][1] = __expf(c[t][1] - mx0); s0 += c[t][1];
                c[t][2] = __expf(c[t][2] - mx1); s1 += c[t][2];
                c[t][3] = __expf(c[t][3] - mx1); s1 += c[t][3];
            }
            #pragma unroll
            for (int o = 1; o <= 2; o <<= 1) {
                s0 += __shfl_xor_sync(~0u, s0, o);
                s1 += __shfl_xor_sync(~0u, s1, o);
            }
            float i0 = 1.0f / s0, i1 = 1.0f / s1;
            #pragma unroll
            for (int t = 0; t < 8; t++) {
                c[t][0] *= i0; c[t][1] *= i0; c[t][2] *= i1; c[t][3] *= i1;
            }
        }
        // P @ V_h : P from logits registers, V via ldmatrix
        float o[4][4];
        #pragma unroll
        for (int dt = 0; dt < 4; dt++) { o[dt][0]=o[dt][1]=o[dt][2]=o[dt][3]=0.f; }
        #pragma unroll
        for (int kc = 0; kc < 4; kc++) {
            unsigned phi[4], plo[4];
            split2(c[2 * kc][0], c[2 * kc][1], phi[0], plo[0]);
            split2(c[2 * kc][2], c[2 * kc][3], phi[1], plo[1]);
            split2(c[2 * kc + 1][0], c[2 * kc + 1][1], phi[2], plo[2]);
            split2(c[2 * kc + 1][2], c[2 * kc + 1][3], phi[3], plo[3]);
            #pragma unroll
            for (int dtp = 0; dtp < 2; dtp++) {
                unsigned vh4[4], vl4[4];
                unsigned ad = (unsigned)(((hh * 32 + dtp * 16 + krc) * VSTR
                                          + kc * 16 + kcol8) * 2);
                ldsm4(vh4, vth_u32 + ad);
                ldsm4(vl4, vtl_u32 + ad);
                mma_bf16(o[2 * dtp], phi, vh4);
                mma_bf16(o[2 * dtp], phi, vl4);
                mma_bf16(o[2 * dtp], plo, vh4);
                mma_bf16(o[2 * dtp + 1], phi, vh4 + 2);
                mma_bf16(o[2 * dtp + 1], phi, vl4 + 2);
                mma_bf16(o[2 * dtp + 1], plo, vh4 + 2);
            }
        }
        #pragma unroll
        for (int dt = 0; dt < 4; dt++) {
            const int col = hh * 32 + dt * 8 + 2 * tig;
            if (r0 < 49) {
                unsigned hi, lo;
                split2(o[dt][0], o[dt][1], hi, lo);
                *(unsigned*)&Ah[r0 * 200 + col] = hi;
                *(unsigned*)&Al[r0 * 200 + col] = lo;
            }
            if (r1 < 49) {
                unsigned hi, lo;
                split2(o[dt][2], o[dt][3], hi, lo);
                *(unsigned*)&Ah[r1 * 200 + col] = hi;
                *(unsigned*)&Al[r1 * 200 + col] = lo;
            }
        }
    }
    __syncthreads();   // attention writes done; WST free

    gemm_mma<0>(g_Phi, g_Plo, proj_b, 1.0f, out + (size_t)b * 9408,
                nullptr, nullptr, nullptr);
}

extern "C" void kernel_launch(void* const* d_in, const int* in_sizes, int n_in,
                              void* d_out, int out_size) {
    const float* x      = (const float*)d_in[0];
    const float* mask   = (const float*)d_in[1];
    const float* qkv_w  = (const float*)d_in[2];
    const float* qkv_b  = (const float*)d_in[3];
    const float* proj_w = (const float*)d_in[4];
    const float* proj_b = (const float*)d_in[5];
    const float* rope   = (const float*)d_in[6];
    float* out = (float*)d_out;

    prep_weights<<<432, 256>>>(qkv_w, proj_w);
    cudaFuncSetAttribute(swin_fused_kernel,
                         cudaFuncAttributeMaxDynamicSharedMemorySize, SMEM_BYTES);
    swin_fused_kernel<<<4096, THREADS, SMEM_BYTES>>>(
        x, mask, qkv_b, proj_b, rope, out);
}

// round 16
// speedup vs baseline: 1.2906x; 1.2906x over previous
#include <cuda_runtime.h>
#include <cuda_bf16.h>
#include <float.h>

#define THREADS 384
// ---- smem byte offsets ----
#define AHI_OFF 0          // x / attn-out hi [56][200] bf16
#define ALO_OFF 22400
#define WST_OFF 44800      // W stage [2buf][2hl][192][48B] = 36864 ; mask aliases
#define QHI_OFF 81664      // Q [56][200] bf16
#define QLO_OFF 104064
#define KHI_OFF 126464     // K [56][200] bf16
#define KLO_OFF 148864
#define VTH_OFF 171264     // V^T [192][72] bf16 (dim-major)
#define VTL_OFF 198912
#define SMEM_BYTES 226560
#define ASTR 200
#define KSTR 200
#define VSTR 72

__device__ __nv_bfloat16 g_Whi[110592];
__device__ __nv_bfloat16 g_Wlo[110592];
__device__ __nv_bfloat16 g_Phi[36864];
__device__ __nv_bfloat16 g_Plo[36864];

__global__ void prep_weights(const float* __restrict__ qkv_w,
                             const float* __restrict__ proj_w) {
    int i = blockIdx.x * 256 + threadIdx.x;
    if (i < 110592) {
        float v = qkv_w[i];
        __nv_bfloat16 h = __float2bfloat16(v);
        g_Whi[i] = h;
        g_Wlo[i] = __float2bfloat16(v - __bfloat162float(h));
    }
    if (i < 36864) {
        float v = proj_w[i];
        __nv_bfloat16 h = __float2bfloat16(v);
        g_Phi[i] = h;
        g_Plo[i] = __float2bfloat16(v - __bfloat162float(h));
    }
}

__device__ __forceinline__ unsigned pkbf(__nv_bfloat16 a, __nv_bfloat16 b) {
    return (unsigned)__bfloat16_as_ushort(a) | ((unsigned)__bfloat16_as_ushort(b) << 16);
}
__device__ __forceinline__ void split2(float x, float y, unsigned& hi, unsigned& lo) {
    __nv_bfloat16 h0 = __float2bfloat16(x), h1 = __float2bfloat16(y);
    __nv_bfloat16 l0 = __float2bfloat16(x - __bfloat162float(h0));
    __nv_bfloat16 l1 = __float2bfloat16(y - __bfloat162float(h1));
    hi = pkbf(h0, h1);
    lo = pkbf(l0, l1);
}
__device__ __forceinline__ void mma_bf16(float* c, const unsigned* a, const unsigned* b) {
    asm volatile(
        "mma.sync.aligned.m16n8k16.row.col.f32.bf16.bf16.f32 "
        "{%0,%1,%2,%3}, {%4,%5,%6,%7}, {%8,%9}, {%0,%1,%2,%3};\n"
        : "+f"(c[0]), "+f"(c[1]), "+f"(c[2]), "+f"(c[3])
        : "r"(a[0]), "r"(a[1]), "r"(a[2]), "r"(a[3]), "r"(b[0]), "r"(b[1]));
}
__device__ __forceinline__ void ldsm4(unsigned* r, unsigned addr) {
    asm volatile("ldmatrix.sync.aligned.m8n8.x4.shared.b16 {%0,%1,%2,%3}, [%4];\n"
                 : "=r"(r[0]), "=r"(r[1]), "=r"(r[2]), "=r"(r[3]) : "r"(addr));
}
__device__ __forceinline__ void ldsm2(unsigned* r, unsigned addr) {
    asm volatile("ldmatrix.sync.aligned.m8n8.x2.shared.b16 {%0,%1}, [%2];\n"
                 : "=r"(r[0]), "=r"(r[1]) : "r"(addr));
}

// ---- generic GEMM: C[49][192] = A(hi+lo)[56][192] @ W^T + bias, scaled ----
// m-tiles rows {0-15,16-31,32-47,40-55} (tile 3 overlaps: duplicate-same writes)
// MODE 0: fp32 -> outp.  MODE 1: RoPE -> bf16 hi/lo (stride KSTR).  MODE 2: V^T.
template <int MODE>
__device__ __noinline__ void gemm_mma(const __nv_bfloat16* __restrict__ Whi,
                                      const __nv_bfloat16* __restrict__ Wlo,
                                      const float* __restrict__ bias, float scale,
                                      float* __restrict__ outp,
                                      __nv_bfloat16* __restrict__ ohi,
                                      __nv_bfloat16* __restrict__ olo,
                                      const float* __restrict__ rope) {
    extern __shared__ char smem[];
    char* wst = smem + WST_OFF;
    const unsigned smem_u32 = (unsigned)__cvta_generic_to_shared(smem);
    const unsigned wst_u32 = smem_u32 + WST_OFF;

    const int tid = threadIdx.x;
    const int wid = tid >> 5, lane = tid & 31;
    const int g = lane >> 2, tig = lane & 3;
    const int mt = wid & 3;
    const int row0 = (mt == 3) ? 40 : mt * 16;
    const int nq = wid >> 2;         // 64-col third
    const int grp = lane >> 3;
    const unsigned lm_off = (unsigned)(((grp >> 1) * 8 + (lane & 7)) * 48 + (grp & 1) * 16);

    const int a_row = row0 + ((grp & 1) << 3) + (lane & 7);
    const int a_col = (grp >> 1) << 3;
    const unsigned a_h = smem_u32 + AHI_OFF + (unsigned)((a_row * ASTR + a_col) * 2);
    const unsigned a_l = smem_u32 + ALO_OFF + (unsigned)((a_row * ASTR + a_col) * 2);

    const int n0 = tid % 192, hf0 = (tid / 192) & 1;
    const int i1 = tid + 384;
    const int n1 = i1 % 192, hf1 = (i1 / 192) & 1;

    float acc[8][4];
    #pragma unroll
    for (int t = 0; t < 8; t++) { acc[t][0]=acc[t][1]=acc[t][2]=acc[t][3]=0.f; }

    {   // stage k-panel 0
        float4 v = *reinterpret_cast<const float4*>(Whi + n0 * 192 + hf0 * 8);
        *reinterpret_cast<float4*>(wst + n0 * 48 + hf0 * 16) = v;
        float4 w = *reinterpret_cast<const float4*>(Wlo + n1 * 192 + hf1 * 8);
        *reinterpret_cast<float4*>(wst + 9216 + n1 * 48 + hf1 * 16) = w;
    }
    __syncthreads();

    for (int k = 0; k < 12; k++) {
        const int buf = k & 1;
        float4 pf0, pf1;
        if (k < 11) {
            pf0 = *reinterpret_cast<const float4*>(Whi + n0 * 192 + (k + 1) * 16 + hf0 * 8);
            pf1 = *reinterpret_cast<const float4*>(Wlo + n1 * 192 + (k + 1) * 16 + hf1 * 8);
        }
        unsigned ahi[4], alo[4];
        ldsm4(ahi, a_h + (unsigned)(k * 32));
        ldsm4(alo, a_l + (unsigned)(k * 32));
        const unsigned base_h = wst_u32 + (unsigned)(buf * 18432) + lm_off;
        #pragma unroll
        for (int p = 0; p < 4; p++) {
            unsigned bh[4], bl[4];
            unsigned ad = base_h + (unsigned)((nq * 64 + 16 * p) * 48);
            ldsm4(bh, ad);
            ldsm4(bl, ad + 9216);
            mma_bf16(acc[2 * p], ahi, bh);
            mma_bf16(acc[2 * p], ahi, bl);
            mma_bf16(acc[2 * p], alo, bh);
            mma_bf16(acc[2 * p + 1], ahi, bh + 2);
            mma_bf16(acc[2 * p + 1], ahi, bl + 2);
            mma_bf16(acc[2 * p + 1], alo, bh + 2);
        }
        if (k < 11) {
            *reinterpret_cast<float4*>(wst + (buf ^ 1) * 18432 + n0 * 48 + hf0 * 16) = pf0;
            *reinterpret_cast<float4*>(wst + (buf ^ 1) * 18432 + 9216 + n1 * 48 + hf1 * 16) = pf1;
            __syncthreads();
        }
    }

    const int r0 = row0 + g;
    #pragma unroll
    for (int t = 0; t < 8; t++) {
        const int col = nq * 64 + t * 8 + 2 * tig;
        float2 bb = *reinterpret_cast<const float2*>(&bias[col]);
        float fx = 0.f, fy = 0.f;
        if (MODE == 1) {
            int hh = col >> 5, d = (col & 31) >> 1;
            fx = rope[hh * 16 + d];
            fy = rope[96 + hh * 16 + d];
        }
        #pragma unroll
        for (int half = 0; half < 2; half++) {
            const int r = r0 + half * 8;
            if (r < 49) {
                float vx = (acc[t][half * 2 + 0] + bb.x) * scale;
                float vy = (acc[t][half * 2 + 1] + bb.y) * scale;
                if (MODE == 0) {
                    *reinterpret_cast<float2*>(&outp[r * 192 + col]) = make_float2(vx, vy);
                } else if (MODE == 1) {
                    float ang = (float)(r % 7) * fx + (float)(r / 7) * fy;
                    float sv, cv;
                    sincosf(ang, &sv, &cv);
                    float re = vx * cv - vy * sv;
                    float im = vx * sv + vy * cv;
                    unsigned hi, lo;
                    split2(re, im, hi, lo);
                    *(unsigned*)&ohi[r * KSTR + col] = hi;
                    *(unsigned*)&olo[r * KSTR + col] = lo;
                } else {
                    __nv_bfloat16 h0 = __float2bfloat16(vx);
                    __nv_bfloat16 l0 = __float2bfloat16(vx - __bfloat162float(h0));
                    __nv_bfloat16 h1 = __float2bfloat16(vy);
                    __nv_bfloat16 l1 = __float2bfloat16(vy - __bfloat162float(h1));
                    ohi[col * VSTR + r] = h0;
                    olo[col * VSTR + r] = l0;
                    ohi[(col + 1) * VSTR + r] = h1;
                    olo[(col + 1) * VSTR + r] = l1;
                }
            }
        }
    }
}

__global__ void __launch_bounds__(THREADS, 1)
swin_fused_kernel(const float* __restrict__ x,
                  const float* __restrict__ mask,
                  const float* __restrict__ qkv_b,
                  const float* __restrict__ proj_b,
                  const float* __restrict__ rope,
                  float* __restrict__ out)
{
    extern __shared__ char smem[];
    __nv_bfloat16* Ah  = (__nv_bfloat16*)(smem + AHI_OFF);
    __nv_bfloat16* Al  = (__nv_bfloat16*)(smem + ALO_OFF);
    __nv_bfloat16* Khi = (__nv_bfloat16*)(smem + KHI_OFF);
    __nv_bfloat16* Klo = (__nv_bfloat16*)(smem + KLO_OFF);
    __nv_bfloat16* Qhi = (__nv_bfloat16*)(smem + QHI_OFF);
    __nv_bfloat16* Qlo = (__nv_bfloat16*)(smem + QLO_OFF);
    float* MSK = (float*)(smem + WST_OFF);
    const unsigned smem_u32 = (unsigned)__cvta_generic_to_shared(smem);
    const int tid = threadIdx.x;
    const int b = blockIdx.x;
    const int lane = tid & 31, wid = tid >> 5;
    const int g = lane >> 2, tig = lane & 3;
    const int grp = lane >> 3;
    const int mt = wid & 3, hh0 = wid >> 2;
    const int row0 = (mt == 3) ? 40 : mt * 16;

    // ---- prologue ----
    for (int i = tid; i < 4704; i += THREADS) {
        int n = i / 96, c = i % 96;
        float2 v = *reinterpret_cast<const float2*>(&x[(size_t)b * 9408 + n * 192 + 2 * c]);
        unsigned hi, lo;
        split2(v.x, v.y, hi, lo);
        *(unsigned*)&Ah[n * ASTR + 2 * c] = hi;
        *(unsigned*)&Al[n * ASTR + 2 * c] = lo;
    }
    for (int i = tid; i < 7 * 96; i += THREADS) {      // A pad rows 49..55
        int r = 49 + i / 96, c = i % 96;
        *(unsigned*)&Ah[r * ASTR + 2 * c] = 0u;
        *(unsigned*)&Al[r * ASTR + 2 * c] = 0u;
    }
    for (int i = tid; i < 7 * 96; i += THREADS) {      // Q pad rows 49..55
        int r = 49 + i / 96, c = i % 96;
        *(unsigned*)&Qhi[r * KSTR + 2 * c] = 0u;
        *(unsigned*)&Qlo[r * KSTR + 2 * c] = 0u;
    }
    for (int i = tid; i < 7 * 96; i += THREADS) {      // K pad rows 49..55
        int r = 49 + i / 96, c = i % 96;
        *(unsigned*)&Khi[r * KSTR + 2 * c] = 0u;
        *(unsigned*)&Klo[r * KSTR + 2 * c] = 0u;
    }
    {   // zero V^T hi+lo (2*27648 B)
        float4* vz = reinterpret_cast<float4*>(smem + VTH_OFF);
        for (int i = tid; i < 3456; i += THREADS) vz[i] = make_float4(0.f, 0.f, 0.f, 0.f);
    }
    // (gemm's first internal __syncthreads orders the fills)

    gemm_mma<1>(g_Whi,         g_Wlo,         qkv_b,       0.17677669529663687f,
                nullptr, Qhi, Qlo, rope);
    gemm_mma<1>(g_Whi + 36864, g_Wlo + 36864, qkv_b + 192, 1.0f,
                nullptr, Khi, Klo, rope);
    gemm_mma<2>(g_Whi + 73728, g_Wlo + 73728, qkv_b + 384, 1.0f, nullptr,
                (__nv_bfloat16*)(smem + VTH_OFF), (__nv_bfloat16*)(smem + VTL_OFF), nullptr);
    __syncthreads();   // all epilogue writes visible; WST idle

    {   // stage shift mask into WST region
        const float* mrow = mask + (size_t)(b & 63) * 2401;
        for (int i = tid; i < 2401; i += THREADS) MSK[i] = mrow[i];
    }
    __syncthreads();

    // ---- barrier-free attention (warp-owned slots), ldmatrix fragments ----
    const int a_row = row0 + ((grp & 1) << 3) + (lane & 7);
    const int a_colblk = (grp >> 1) << 3;
    const unsigned q_h = smem_u32 + QHI_OFF + (unsigned)((a_row * KSTR + a_colblk) * 2);
    const unsigned q_l = smem_u32 + QLO_OFF + (unsigned)((a_row * KSTR + a_colblk) * 2);
    const int krc = ((grp >> 1) << 3) + (lane & 7);
    const int kcol8 = (grp & 1) << 3;
    const unsigned khi_u32 = smem_u32 + KHI_OFF;
    const unsigned klo_u32 = smem_u32 + KLO_OFF;
    const unsigned vth_u32 = smem_u32 + VTH_OFF;
    const unsigned vtl_u32 = smem_u32 + VTL_OFF;
    const int r0 = row0 + g;
    const int r1 = r0 + 8;

    #pragma unroll 1
    for (int si = 0; si < 2; si++) {
        const int hh = hh0 + 3 * si;
        float c[8][4];
        #pragma unroll
        for (int t = 0; t < 7; t++) { c[t][0]=c[t][1]=c[t][2]=c[t][3]=0.f; }
        c[7][0] = c[7][1] = c[7][2] = c[7][3] = -FLT_MAX;

        // logits: Q (ldmatrix) @ K^T (ldmatrix)
        #pragma unroll
        for (int kc = 0; kc < 2; kc++) {
            const int kb0 = hh * 32 + kc * 16;
            unsigned qhf[4], qlf[4];
            ldsm4(qhf, q_h + (unsigned)(kb0 * 2));
            ldsm4(qlf, q_l + (unsigned)(kb0 * 2));
            #pragma unroll
            for (int tp = 0; tp < 3; tp++) {
                unsigned kh4[4], kl4[4];
                unsigned ad = (unsigned)(((16 * tp + krc) * KSTR + kb0 + kcol8) * 2);
                ldsm4(kh4, khi_u32 + ad);
                ldsm4(kl4, klo_u32 + ad);
                mma_bf16(c[2 * tp], qhf, kh4);
                mma_bf16(c[2 * tp], qhf, kl4);
                mma_bf16(c[2 * tp], qlf, kh4);
                mma_bf16(c[2 * tp + 1], qhf, kh4 + 2);
                mma_bf16(c[2 * tp + 1], qhf, kl4 + 2);
                mma_bf16(c[2 * tp + 1], qlf, kh4 + 2);
            }
            {   // token tile 6 (rows 48..55) via x2
                unsigned kh2[2], kl2[2];
                unsigned ad = (unsigned)(((48 + (lane & 7)) * KSTR + kb0 + ((grp & 1) << 3)) * 2);
                ldsm2(kh2, khi_u32 + ad);
                ldsm2(kl2, klo_u32 + ad);
                mma_bf16(c[6], qhf, kh2);
                mma_bf16(c[6], qhf, kl2);
                mma_bf16(c[6], qlf, kh2);
            }
        }
        // mask add + column bounds
        #pragma unroll
        for (int t = 0; t < 7; t++) {
            const int col = t * 8 + 2 * tig;
            if (col < 49) {
                if (r0 < 49) c[t][0] += MSK[r0 * 49 + col];
                if (r1 < 49) c[t][2] += MSK[r1 * 49 + col];
            } else { c[t][0] = -FLT_MAX; c[t][2] = -FLT_MAX; }
            if (col + 1 < 49) {
                if (r0 < 49) c[t][1] += MSK[r0 * 49 + col + 1];
                if (r1 < 49) c[t][3] += MSK[r1 * 49 + col + 1];
            } else { c[t][1] = -FLT_MAX; c[t][3] = -FLT_MAX; }
        }
        // softmax (row lives in a quad: 2 shuffles per reduction)
        {
            float mx0 = -FLT_MAX, mx1 = -FLT_MAX;
            #pragma unroll
            for (int t = 0; t < 8; t++) {
                mx0 = fmaxf(mx0, fmaxf(c[t][0], c[t][1]));
                mx1 = fmaxf(mx1, fmaxf(c[t][2], c[t][3]));
            }
            #pragma unroll
            for (int o = 1; o <= 2; o <<= 1) {
                mx0 = fmaxf(mx0, __shfl_xor_sync(~0u, mx0, o));
                mx1 = fmaxf(mx1, __shfl_xor_sync(~0u, mx1, o));
            }
            float s0 = 0.f, s1 = 0.f;
            #pragma unroll
            for (int t = 0; t < 8; t++) {
                c[t][0] = __expf(c[t][0] - mx0); s0 += c[t][0];
                c[t][1] = __expf(c[t][1] - mx0); s0 += c[t][1];
                c[t][2] = __expf(c[t][2] - mx1); s1 += c[t][2];
                c[t][3] = __expf(c[t][3] - mx1); s1 += c[t][3];
            }
            #pragma unroll
            for (int o = 1; o <= 2; o <<= 1) {
                s0 += __shfl_xor_sync(~0u, s0, o);
                s1 += __shfl_xor_sync(~0u, s1, o);
            }
            float i0 = 1.0f / s0, i1 = 1.0f / s1;
            #pragma unroll
            for (int t = 0; t < 8; t++) {
                c[t][0] *= i0; c[t][1] *= i0; c[t][2] *= i1; c[t][3] *= i1;
            }
        }
        // P @ V_h : P from logits registers, V via ldmatrix
        float o[4][4];
        #pragma unroll
        for (int dt = 0; dt < 4; dt++) { o[dt][0]=o[dt][1]=o[dt][2]=o[dt][3]=0.f; }
        #pragma unroll
        for (int kc = 0; kc < 4; kc++) {
            unsigned phi[4], plo[4];
            split2(c[2 * kc][0], c[2 * kc][1], phi[0], plo[0]);
            split2(c[2 * kc][2], c[2 * kc][3], phi[1], plo[1]);
            split2(c[2 * kc + 1][0], c[2 * kc + 1][1], phi[2], plo[2]);
            split2(c[2 * kc + 1][2], c[2 * kc + 1][3], phi[3], plo[3]);
            #pragma unroll
            for (int dtp = 0; dtp < 2; dtp++) {
                unsigned vh4[4], vl4[4];
                unsigned ad = (unsigned)(((hh * 32 + dtp * 16 + krc) * VSTR
                                          + kc * 16 + kcol8) * 2);
                ldsm4(vh4, vth_u32 + ad);
                ldsm4(vl4, vtl_u32 + ad);
                mma_bf16(o[2 * dtp], phi, vh4);
                mma_bf16(o[2 * dtp], phi, vl4);
                mma_bf16(o[2 * dtp], plo, vh4);
                mma_bf16(o[2 * dtp + 1], phi, vh4 + 2);
                mma_bf16(o[2 * dtp + 1], phi, vl4 + 2);
                mma_bf16(o[2 * dtp + 1], plo, vh4 + 2);
            }
        }
        #pragma unroll
        for (int dt = 0; dt < 4; dt++) {
            const int col = hh * 32 + dt * 8 + 2 * tig;
            if (r0 < 49) {
                unsigned hi, lo;
                split2(o[dt][0], o[dt][1], hi, lo);
                *(unsigned*)&Ah[r0 * ASTR + col] = hi;
                *(unsigned*)&Al[r0 * ASTR + col] = lo;
            }
            if (r1 < 49) {
                unsigned hi, lo;
                split2(o[dt][2], o[dt][3], hi, lo);
                *(unsigned*)&Ah[r1 * ASTR + col] = hi;
                *(unsigned*)&Al[r1 * ASTR + col] = lo;
            }
        }
    }
    __syncthreads();   // attention writes done; WST free

    gemm_mma<0>(g_Phi, g_Plo, proj_b, 1.0f, out + (size_t)b * 9408,
                nullptr, nullptr, nullptr);
}

extern "C" void kernel_launch(void* const* d_in, const int* in_sizes, int n_in,
                              void* d_out, int out_size) {
    const float* x      = (const float*)d_in[0];
    const float* mask   = (const float*)d_in[1];
    const float* qkv_w  = (const float*)d_in[2];
    const float* qkv_b  = (const float*)d_in[3];
    const float* proj_w = (const float*)d_in[4];
    const float* proj_b = (const float*)d_in[5];
    const float* rope   = (const float*)d_in[6];
    float* out = (float*)d_out;

    prep_weights<<<432, 256>>>(qkv_w, proj_w);
    cudaFuncSetAttribute(swin_fused_kernel,
                         cudaFuncAttributeMaxDynamicSharedMemorySize, SMEM_BYTES);
    swin_fused_kernel<<<4096, THREADS, SMEM_BYTES>>>(
        x, mask, qkv_b, proj_b, rope, out);
}